// round 15
// baseline (speedup 1.0000x reference)
#include <cuda_runtime.h>
#include <cuda_bf16.h>
#include <cuda_fp16.h>
#include <math.h>

#define Bsz 2
#define Sdim 2048
#define Edim 1024
#define Hn 16
#define DHd 64
#define Adim 1024
#define Mrows (Bsz * Sdim)  // 4096

typedef unsigned short ushort_t;

// Scratch (allocation-free rule: __device__ globals)
__device__ __align__(256) float    g_Q [(size_t)Bsz * Hn * Sdim * DHd];  // [B,H,S,DH] fp32
__device__ __align__(256) ushort_t g_Kf[(size_t)Bsz * Hn * Sdim * DHd];  // K fp16
__device__ __align__(256) ushort_t g_Vf[(size_t)Bsz * Hn * Sdim * DHd];  // V fp16
__device__ __align__(256) ushort_t g_Of[(size_t)Bsz * Sdim * Adim];      // attn out fp16
// pre-converted inputs (single fp16)
__device__ __align__(256) ushort_t g_xf [(size_t)Mrows * Edim];
__device__ __align__(256) ushort_t g_Wqf[(size_t)Hn * Edim * DHd];
__device__ __align__(256) ushort_t g_Wkf[(size_t)Hn * Edim * DHd];
__device__ __align__(256) ushort_t g_Wvf[(size_t)Hn * Edim * DHd];
__device__ __align__(256) ushort_t g_Wof[(size_t)Adim * Edim];

// ---- mma.sync helpers --------------------------------------------------
__device__ __forceinline__ void ldsm_x4(unsigned* r, const void* p) {
    unsigned addr = (unsigned)__cvta_generic_to_shared(p);
    asm volatile("ldmatrix.sync.aligned.m8n8.x4.shared.b16 {%0,%1,%2,%3}, [%4];"
        : "=r"(r[0]), "=r"(r[1]), "=r"(r[2]), "=r"(r[3]) : "r"(addr));
}
__device__ __forceinline__ void ldsm_x4_t(unsigned* r, const void* p) {
    unsigned addr = (unsigned)__cvta_generic_to_shared(p);
    asm volatile("ldmatrix.sync.aligned.m8n8.x4.trans.shared.b16 {%0,%1,%2,%3}, [%4];"
        : "=r"(r[0]), "=r"(r[1]), "=r"(r[2]), "=r"(r[3]) : "r"(addr));
}
__device__ __forceinline__ void mma_f16(float* c, const unsigned* a, const unsigned* b) {
    asm volatile("mma.sync.aligned.m16n8k16.row.col.f32.f16.f16.f32 "
        "{%0,%1,%2,%3}, {%4,%5,%6,%7}, {%8,%9}, {%0,%1,%2,%3};"
        : "+f"(c[0]), "+f"(c[1]), "+f"(c[2]), "+f"(c[3])
        : "r"(a[0]), "r"(a[1]), "r"(a[2]), "r"(a[3]), "r"(b[0]), "r"(b[1]));
}
// fp16 hi/lo pair (attention Q only)
__device__ __forceinline__ void hilo_pair_f16(float x, float y, unsigned& h, unsigned& l) {
    __half hx = __float2half_rn(x), hy = __float2half_rn(y);
    float rx = x - __half2float(hx), ry = y - __half2float(hy);
    __half lx = __float2half_rn(rx), ly = __float2half_rn(ry);
    h = (unsigned)__half_as_ushort(hx) | ((unsigned)__half_as_ushort(hy) << 16);
    l = (unsigned)__half_as_ushort(lx) | ((unsigned)__half_as_ushort(ly) << 16);
}
__device__ __forceinline__ unsigned pkf16(float x, float y) {
    __half2 h = __floats2half2_rn(x, y);
    return *(unsigned*)&h;
}
__device__ __forceinline__ float ex2f(float x) {
    float y; asm("ex2.approx.ftz.f32 %0, %1;" : "=f"(y) : "f"(x)); return y;
}
// ---- cp.async ----
__device__ __forceinline__ void cp_async16(void* smem_dst, const void* gmem_src) {
    unsigned d = (unsigned)__cvta_generic_to_shared(smem_dst);
    asm volatile("cp.async.cg.shared.global [%0], [%1], 16;" :: "r"(d), "l"(gmem_src));
}
__device__ __forceinline__ void cp_commit() {
    asm volatile("cp.async.commit_group;" ::: "memory");
}
__device__ __forceinline__ void cp_wait0() {
    asm volatile("cp.async.wait_group 0;" ::: "memory");
}

// ---------------------------------------------------------------------------
// Kernel 0: convert x + 4 weights fp32 -> single fp16, ONE launch.
// ---------------------------------------------------------------------------
__global__ __launch_bounds__(256) void split5_kernel(
    const float* __restrict__ s0, const float* __restrict__ s1,
    const float* __restrict__ s2, const float* __restrict__ s3,
    const float* __restrict__ s4, int nW, int nX)
{
    int i = blockIdx.x * blockDim.x + threadIdx.x;
    const float* src;
    ushort_t* df;
    int n4;
    switch (blockIdx.y) {
        case 0: src = s0; df = g_Wqf; n4 = nW; break;
        case 1: src = s1; df = g_Wkf; n4 = nW; break;
        case 2: src = s2; df = g_Wvf; n4 = nW; break;
        case 3: src = s3; df = g_Wof; n4 = nW; break;
        default: src = s4; df = g_xf; n4 = nX; break;
    }
    if (i >= n4) return;
    float4 v = *(const float4*)(src + (size_t)i * 4);
    *(uint2*)(df + (size_t)i * 4) = make_uint2(pkf16(v.x, v.y), pkf16(v.z, v.w));
}

// ---------------------------------------------------------------------------
// Kernel 1: fused QKV projection, pure fp16 GEMM with cp.async staging and
// k-step 32 (one barrier pair per 32 k). Epilogue: Q fp32, K/V fp16.
// ---------------------------------------------------------------------------
__global__ __launch_bounds__(256) void qkv_kernel(
    const float* __restrict__ bq, const float* __restrict__ bk,
    const float* __restrict__ bv)
{
    __shared__ __align__(16) ushort_t As_f[2][128][40];  // [buf][m][k 32+8 pad]
    __shared__ __align__(16) ushort_t Bs_f[2][32][136];  // [buf][k][n 128+8 pad]

    const int tid = threadIdx.x;
    const int lane = tid & 31;
    const int warp = tid >> 5;
    const int wm = warp & 1;
    const int wn = warp >> 1;
    const int m0 = blockIdx.x * 128;
    const int n0 = blockIdx.y * 128;
    const int z = n0 >> 10;
    const ushort_t* Wf = (z == 0 ? g_Wqf : (z == 1 ? g_Wkf : g_Wvf));
    const float* bias  = (z == 0 ? bq : (z == 1 ? bk : bv));

    // staging chunk descriptors (2 chunks each for A and B per thread)
    // A chunk c (0..511): row = c>>2, kc = (c&3)*8
    const int a0row = tid >> 2,          a0kc = (tid & 3) * 8;
    const int a1row = (tid + 256) >> 2,  a1kc = ((tid + 256) & 3) * 8;
    const ushort_t* Ag0 = g_xf + (size_t)(m0 + a0row) * Edim + a0kc;
    const ushort_t* Ag1 = g_xf + (size_t)(m0 + a1row) * Edim + a1kc;
    // B chunk c (0..511): krow = c>>4, nc = (c&15)*8  (8-wide chunk stays in one head)
    const int b0k = tid >> 4,            b0n = (tid & 15) * 8;
    const int b1k = (tid + 256) >> 4,    b1n = ((tid + 256) & 15) * 8;
    const int cB0 = n0 + b0n, cB1 = n0 + b1n;
    const ushort_t* Bg0 = Wf + (size_t)((cB0 >> 6) & 15) * (Edim * DHd) + (cB0 & 63);
    const ushort_t* Bg1 = Wf + (size_t)((cB1 >> 6) & 15) * (Edim * DHd) + (cB1 & 63);

    float C[4][4][4];
#pragma unroll
    for (int i = 0; i < 4; i++)
#pragma unroll
        for (int j = 0; j < 4; j++)
#pragma unroll
            for (int e = 0; e < 4; e++) C[i][j][e] = 0.f;

    // stage k-tile 0 into buffer 0
    cp_async16(&As_f[0][a0row][a0kc], Ag0);
    cp_async16(&As_f[0][a1row][a1kc], Ag1);
    cp_async16(&Bs_f[0][b0k][b0n], Bg0 + (size_t)b0k * DHd);
    cp_async16(&Bs_f[0][b1k][b1n], Bg1 + (size_t)b1k * DHd);
    cp_commit();

    const int lrow = lane & 15;
    const int lk8 = (lane >> 4) * 8;

    int buf = 0;
    for (int k0 = 0; k0 < Edim; k0 += 32) {
        cp_wait0();
        __syncthreads();

        if (k0 + 32 < Edim) {
            int nb = buf ^ 1;
            cp_async16(&As_f[nb][a0row][a0kc], Ag0 + k0 + 32);
            cp_async16(&As_f[nb][a1row][a1kc], Ag1 + k0 + 32);
            cp_async16(&Bs_f[nb][b0k][b0n], Bg0 + (size_t)(k0 + 32 + b0k) * DHd);
            cp_async16(&Bs_f[nb][b1k][b1n], Bg1 + (size_t)(k0 + 32 + b1k) * DHd);
            cp_commit();
        }

#pragma unroll
        for (int kh = 0; kh < 2; kh++) {
            unsigned a_f[4][4], b_f[4][2];
#pragma unroll
            for (int mi = 0; mi < 4; mi++)
                ldsm_x4(a_f[mi], &As_f[buf][wm * 64 + mi * 16 + lrow][kh * 16 + lk8]);
#pragma unroll
            for (int np = 0; np < 2; np++) {
                unsigned r[4];
                ldsm_x4_t(r, &Bs_f[buf][kh * 16 + lrow][wn * 32 + np * 16 + lk8]);
                b_f[2*np][0] = r[0]; b_f[2*np][1] = r[1];
                b_f[2*np+1][0] = r[2]; b_f[2*np+1][1] = r[3];
            }
#pragma unroll
            for (int mi = 0; mi < 4; mi++)
#pragma unroll
                for (int ni = 0; ni < 4; ni++)
                    mma_f16(C[mi][ni], a_f[mi], b_f[ni]);
        }
        __syncthreads();
        buf ^= 1;
    }

    // epilogue: Q fp32; K fp16; V fp16 (R14-identical)
#pragma unroll
    for (int mi = 0; mi < 4; mi++)
#pragma unroll
        for (int ni = 0; ni < 4; ni++) {
            int gm = m0 + wm * 64 + mi * 16 + (lane >> 2);
            int gc = n0 + wn * 32 + ni * 8 + (lane & 3) * 2;
            float b0f = bias[gc & 1023];
            float b1f = bias[(gc & 1023) + 1];
            int h = (gc >> 6) & 15;
            int d = gc & 63;
            int bb = gm >> 11, s = gm & (Sdim - 1);
            size_t off0 = ((size_t)(bb * Hn + h) * Sdim + s) * DHd + d;
            int gm2 = gm + 8;
            int bb2 = gm2 >> 11, s2 = gm2 & (Sdim - 1);
            size_t off1 = ((size_t)(bb2 * Hn + h) * Sdim + s2) * DHd + d;
            float v00 = C[mi][ni][0] + b0f, v01 = C[mi][ni][1] + b1f;
            float v10 = C[mi][ni][2] + b0f, v11 = C[mi][ni][3] + b1f;
            if (z == 0) {
                *(float2*)(g_Q + off0) = make_float2(v00, v01);
                *(float2*)(g_Q + off1) = make_float2(v10, v11);
            } else {
                ushort_t* dst = (z == 1 ? g_Kf : g_Vf);
                *(unsigned*)(dst + off0) = pkf16(v00, v01);
                *(unsigned*)(dst + off1) = pkf16(v10, v11);
            }
        }
}

// ---------------------------------------------------------------------------
// Kernel 2: flash attention, fp16 (R14-proven, unchanged).
// ---------------------------------------------------------------------------
#define ATILE 4608            // 64*72 ushorts per array
#define ABUF  (2 * ATILE)
#define ATTN_SMEM_BYTES (2 * ABUF * 2)   // 36,864 B

__global__ __launch_bounds__(256) void attn_kernel()
{
    extern __shared__ ushort_t asmem[];

    const int bh = blockIdx.y;
    const int tid = threadIdx.x;
    const int lane = tid & 31;
    const int warp = tid >> 5;

    const float* Qp = g_Q + (size_t)bh * Sdim * DHd;
    const ushort_t* Kp = g_Kf + (size_t)bh * Sdim * DHd;
    const ushort_t* Vp = g_Vf + (size_t)bh * Sdim * DHd;

    const float SCALE = 0.125f * 1.4426950408889634f;

    unsigned aq_h[4][4], aq_l[4][4];
    {
        const int r0 = blockIdx.x * 128 + warp * 16 + (lane >> 2);
        const int r1 = r0 + 8;
        const int cb = (lane & 3) * 2;
#pragma unroll
        for (int kk = 0; kk < 4; kk++) {
            float2 v00 = *(const float2*)(Qp + (size_t)r0 * DHd + kk * 16 + cb);
            float2 v01 = *(const float2*)(Qp + (size_t)r0 * DHd + kk * 16 + cb + 8);
            float2 v10 = *(const float2*)(Qp + (size_t)r1 * DHd + kk * 16 + cb);
            float2 v11 = *(const float2*)(Qp + (size_t)r1 * DHd + kk * 16 + cb + 8);
            hilo_pair_f16(v00.x * SCALE, v00.y * SCALE, aq_h[kk][0], aq_l[kk][0]);
            hilo_pair_f16(v10.x * SCALE, v10.y * SCALE, aq_h[kk][1], aq_l[kk][1]);
            hilo_pair_f16(v01.x * SCALE, v01.y * SCALE, aq_h[kk][2], aq_l[kk][2]);
            hilo_pair_f16(v11.x * SCALE, v11.y * SCALE, aq_h[kk][3], aq_l[kk][3]);
        }
    }

    float o[8][4];
#pragma unroll
    for (int i = 0; i < 8; i++)
#pragma unroll
        for (int e = 0; e < 4; e++) o[i][e] = 0.f;
    float m0_ = -INFINITY, m1_ = -INFINITY, l0_ = 0.f, l1_ = 0.f;

    const int l15 = lane & 15;
    const int lk8 = (lane >> 4) * 8;
    const int srow = tid >> 3;
    const int sc8 = (tid & 7) * 8;

#pragma unroll
    for (int i = 0; i < 2; i++) {
        int row = srow + i * 32;
        size_t goff = (size_t)row * DHd + sc8;
        int soff = row * 72 + sc8;
        cp_async16(&asmem[0 * ABUF + 0 * ATILE + soff], Kp + goff);
        cp_async16(&asmem[0 * ABUF + 1 * ATILE + soff], Vp + goff);
    }
    cp_commit();

    int buf = 0;
    for (int t0 = 0; t0 < Sdim; t0 += 64) {
        cp_wait0();
        __syncthreads();

        const ushort_t* Ks = asmem + buf * ABUF + 0 * ATILE;
        const ushort_t* Vs = asmem + buf * ABUF + 1 * ATILE;

        if (t0 + 64 < Sdim) {
            int nb = buf ^ 1;
#pragma unroll
            for (int i = 0; i < 2; i++) {
                int row = srow + i * 32;
                size_t goff = (size_t)(t0 + 64 + row) * DHd + sc8;
                int soff = row * 72 + sc8;
                cp_async16(&asmem[nb * ABUF + 0 * ATILE + soff], Kp + goff);
                cp_async16(&asmem[nb * ABUF + 1 * ATILE + soff], Vp + goff);
            }
            cp_commit();
        }

        float sc[8][4];
#pragma unroll
        for (int i = 0; i < 8; i++)
#pragma unroll
            for (int e = 0; e < 4; e++) sc[i][e] = 0.f;

#pragma unroll
        for (int kk = 0; kk < 4; kk++) {
#pragma unroll
            for (int pp = 0; pp < 4; pp++) {
                unsigned rk[4];
                ldsm_x4(rk, &Ks[(pp * 16 + l15) * 72 + kk * 16 + lk8]);
                unsigned bk0[2] = {rk[0], rk[2]}, bk1[2] = {rk[1], rk[3]};
                mma_f16(sc[2*pp],   aq_h[kk], bk0);
                mma_f16(sc[2*pp],   aq_l[kk], bk0);
                mma_f16(sc[2*pp+1], aq_h[kk], bk1);
                mma_f16(sc[2*pp+1], aq_l[kk], bk1);
            }
        }

        float mx0 = m0_, mx1 = m1_;
#pragma unroll
        for (int i = 0; i < 8; i++) {
            mx0 = fmaxf(mx0, fmaxf(sc[i][0], sc[i][1]));
            mx1 = fmaxf(mx1, fmaxf(sc[i][2], sc[i][3]));
        }
        mx0 = fmaxf(mx0, __shfl_xor_sync(0xffffffffu, mx0, 1));
        mx0 = fmaxf(mx0, __shfl_xor_sync(0xffffffffu, mx0, 2));
        mx1 = fmaxf(mx1, __shfl_xor_sync(0xffffffffu, mx1, 1));
        mx1 = fmaxf(mx1, __shfl_xor_sync(0xffffffffu, mx1, 2));
        if (mx0 > m0_) {
            float corr = ex2f(m0_ - mx0);
            m0_ = mx0; l0_ *= corr;
#pragma unroll
            for (int i = 0; i < 8; i++) { o[i][0] *= corr; o[i][1] *= corr; }
        }
        if (mx1 > m1_) {
            float corr = ex2f(m1_ - mx1);
            m1_ = mx1; l1_ *= corr;
#pragma unroll
            for (int i = 0; i < 8; i++) { o[i][2] *= corr; o[i][3] *= corr; }
        }
        float ts0 = 0.f, ts1 = 0.f;
#pragma unroll
        for (int i = 0; i < 8; i++) {
            sc[i][0] = ex2f(sc[i][0] - m0_);
            sc[i][1] = ex2f(sc[i][1] - m0_);
            sc[i][2] = ex2f(sc[i][2] - m1_);
            sc[i][3] = ex2f(sc[i][3] - m1_);
            ts0 += sc[i][0] + sc[i][1];
            ts1 += sc[i][2] + sc[i][3];
        }
        ts0 += __shfl_xor_sync(0xffffffffu, ts0, 1);
        ts0 += __shfl_xor_sync(0xffffffffu, ts0, 2);
        ts1 += __shfl_xor_sync(0xffffffffu, ts1, 1);
        ts1 += __shfl_xor_sync(0xffffffffu, ts1, 2);
        l0_ += ts0; l1_ += ts1;

        // --- O += P @ V: both single fp16 ---
#pragma unroll
        for (int ss = 0; ss < 4; ss++) {
            unsigned ap[4];
            ap[0] = pkf16(sc[2*ss][0],   sc[2*ss][1]);
            ap[1] = pkf16(sc[2*ss][2],   sc[2*ss][3]);
            ap[2] = pkf16(sc[2*ss+1][0], sc[2*ss+1][1]);
            ap[3] = pkf16(sc[2*ss+1][2], sc[2*ss+1][3]);
#pragma unroll
            for (int np = 0; np < 4; np++) {
                unsigned vv[4];
                ldsm_x4_t(vv, &Vs[(ss * 16 + l15) * 72 + np * 16 + lk8]);
                unsigned b0[2] = {vv[0], vv[1]}, b1[2] = {vv[2], vv[3]};
                mma_f16(o[2*np],   ap, b0);
                mma_f16(o[2*np+1], ap, b1);
            }
        }
        __syncthreads();
        buf ^= 1;
    }

    // write normalized O as fp16 to g_Of
    const float inv0 = 1.0f / l0_, inv1 = 1.0f / l1_;
    const int b = bh >> 4, h = bh & 15;
    const int r0 = blockIdx.x * 128 + warp * 16 + (lane >> 2);
    size_t base0 = (size_t)(b * Sdim + r0) * Adim + h * DHd;
    size_t base1 = (size_t)(b * Sdim + r0 + 8) * Adim + h * DHd;
#pragma unroll
    for (int np = 0; np < 8; np++) {
        int col = np * 8 + (lane & 3) * 2;
        *(unsigned*)(g_Of + base0 + col) = pkf16(o[np][0] * inv0, o[np][1] * inv0);
        *(unsigned*)(g_Of + base1 + col) = pkf16(o[np][2] * inv1, o[np][3] * inv1);
    }
}

// ---------------------------------------------------------------------------
// Kernel 3: output projection, fp16 GEMM with cp.async staging + k-step 32.
// ---------------------------------------------------------------------------
__global__ __launch_bounds__(256) void outproj_kernel(
    const float* __restrict__ bo, float* __restrict__ out)
{
    __shared__ __align__(16) ushort_t As_f[2][128][40];
    __shared__ __align__(16) ushort_t Bs_f[2][32][136];

    const int tid = threadIdx.x;
    const int lane = tid & 31;
    const int warp = tid >> 5;
    const int wm = warp & 1;
    const int wn = warp >> 1;
    const int m0 = blockIdx.x * 128;
    const int n0 = blockIdx.y * 128;

    const int a0row = tid >> 2,          a0kc = (tid & 3) * 8;
    const int a1row = (tid + 256) >> 2,  a1kc = ((tid + 256) & 3) * 8;
    const ushort_t* Ag0 = g_Of + (size_t)(m0 + a0row) * Adim + a0kc;
    const ushort_t* Ag1 = g_Of + (size_t)(m0 + a1row) * Adim + a1kc;
    const int b0k = tid >> 4,            b0n = (tid & 15) * 8;
    const int b1k = (tid + 256) >> 4,    b1n = ((tid + 256) & 15) * 8;
    const ushort_t* Bg0 = g_Wof + n0 + b0n;
    const ushort_t* Bg1 = g_Wof + n0 + b1n;

    float C[4][4][4];
#pragma unroll
    for (int i = 0; i < 4; i++)
#pragma unroll
        for (int j = 0; j < 4; j++)
#pragma unroll
            for (int e = 0; e < 4; e++) C[i][j][e] = 0.f;

    cp_async16(&As_f[0][a0row][a0kc], Ag0);
    cp_async16(&As_f[0][a1row][a1kc], Ag1);
    cp_async16(&Bs_f[0][b0k][b0n], Bg0 + (size_t)b0k * Edim);
    cp_async16(&Bs_f[0][b1k][b1n], Bg1 + (size_t)b1k * Edim);
    cp_commit();

    const int lrow = lane & 15;
    const int lk8 = (lane >> 4) * 8;

    int buf = 0;
    for (int k0 = 0; k0 < Adim; k0 += 32) {
        cp_wait0();
        __syncthreads();

        if (k0 + 32 < Adim) {
            int nb = buf ^ 1;
            cp_async16(&As_f[nb][a0row][a0kc], Ag0 + k0 + 32);
            cp_async16(&As_f[nb][a1row][a1kc], Ag1 + k0 + 32);
            cp_async16(&Bs_f[nb][b0k][b0n], Bg0 + (size_t)(k0 + 32 + b0k) * Edim);
            cp_async16(&Bs_f[nb][b1k][b1n], Bg1 + (size_t)(k0 + 32 + b1k) * Edim);
            cp_commit();
        }

#pragma unroll
        for (int kh = 0; kh < 2; kh++) {
            unsigned a_f[4][4], b_f[4][2];
#pragma unroll
            for (int mi = 0; mi < 4; mi++)
                ldsm_x4(a_f[mi], &As_f[buf][wm * 64 + mi * 16 + lrow][kh * 16 + lk8]);
#pragma unroll
            for (int np = 0; np < 2; np++) {
                unsigned r[4];
                ldsm_x4_t(r, &Bs_f[buf][kh * 16 + lrow][wn * 32 + np * 16 + lk8]);
                b_f[2*np][0] = r[0]; b_f[2*np][1] = r[1];
                b_f[2*np+1][0] = r[2]; b_f[2*np+1][1] = r[3];
            }
#pragma unroll
            for (int mi = 0; mi < 4; mi++)
#pragma unroll
                for (int ni = 0; ni < 4; ni++)
                    mma_f16(C[mi][ni], a_f[mi], b_f[ni]);
        }
        __syncthreads();
        buf ^= 1;
    }

#pragma unroll
    for (int mi = 0; mi < 4; mi++)
#pragma unroll
        for (int ni = 0; ni < 4; ni++) {
            int gm = m0 + wm * 64 + mi * 16 + (lane >> 2);
            int gc = n0 + wn * 32 + ni * 8 + (lane & 3) * 2;
            float b0f = bo[gc], b1f = bo[gc + 1];
            float* p0 = out + (size_t)gm * Edim + gc;
            *(float2*)p0 = make_float2(C[mi][ni][0] + b0f, C[mi][ni][1] + b1f);
            float* p1 = out + (size_t)(gm + 8) * Edim + gc;
            *(float2*)p1 = make_float2(C[mi][ni][2] + b0f, C[mi][ni][3] + b1f);
        }
}

extern "C" void kernel_launch(void* const* d_in, const int* in_sizes, int n_in,
                              void* d_out, int out_size)
{
    const float* x  = (const float*)d_in[0];
    const float* Wq = (const float*)d_in[1];
    const float* bq = (const float*)d_in[2];
    const float* Wk = (const float*)d_in[3];
    const float* bk = (const float*)d_in[4];
    const float* Wv = (const float*)d_in[5];
    const float* bv = (const float*)d_in[6];
    const float* Wo = (const float*)d_in[7];
    const float* bo = (const float*)d_in[8];
    float* out = (float*)d_out;

    static bool attr_set = false;
    if (!attr_set) {
        cudaFuncSetAttribute(attn_kernel,
            cudaFuncAttributeMaxDynamicSharedMemorySize, ATTN_SMEM_BYTES);
        attr_set = true;
    }

    const int nW = Hn * Edim * DHd / 4;           // 262,144 float4s per weight
    const int nX = Mrows * Edim / 4;              // 1,048,576 float4s
    dim3 g0((nX + 255) / 256, 5);
    split5_kernel<<<g0, 256>>>(Wq, Wk, Wv, Wo, x, nW, nX);

    dim3 g1(Mrows / 128, (3 * Hn * DHd) / 128);   // (32, 24)
    qkv_kernel<<<g1, 256>>>(bq, bk, bv);

    dim3 g2(Sdim / 128, Bsz * Hn);                // (16, 32)
    attn_kernel<<<g2, 256, ATTN_SMEM_BYTES>>>();

    dim3 g3(Mrows / 128, Edim / 128);             // (32, 8)
    outproj_kernel<<<g3, 256>>>(bo, out);
}

// round 16
// speedup vs baseline: 1.4649x; 1.4649x over previous
#include <cuda_runtime.h>
#include <cuda_bf16.h>
#include <cuda_fp16.h>
#include <math.h>

#define Bsz 2
#define Sdim 2048
#define Edim 1024
#define Hn 16
#define DHd 64
#define Adim 1024
#define Mrows (Bsz * Sdim)  // 4096

typedef unsigned short ushort_t;

// Scratch (allocation-free rule: __device__ globals)
__device__ __align__(256) float    g_Q [(size_t)Bsz * Hn * Sdim * DHd];  // [B,H,S,DH] fp32
__device__ __align__(256) ushort_t g_Kf[(size_t)Bsz * Hn * Sdim * DHd];  // K fp16
__device__ __align__(256) ushort_t g_Vf[(size_t)Bsz * Hn * Sdim * DHd];  // V fp16
__device__ __align__(256) ushort_t g_Of[(size_t)Bsz * Sdim * Adim];      // attn out fp16
// pre-converted inputs (single fp16)
__device__ __align__(256) ushort_t g_xf [(size_t)Mrows * Edim];
__device__ __align__(256) ushort_t g_Wqf[(size_t)Hn * Edim * DHd];
__device__ __align__(256) ushort_t g_Wkf[(size_t)Hn * Edim * DHd];
__device__ __align__(256) ushort_t g_Wvf[(size_t)Hn * Edim * DHd];
__device__ __align__(256) ushort_t g_Wof[(size_t)Adim * Edim];

// ---- mma.sync helpers --------------------------------------------------
__device__ __forceinline__ void ldsm_x4(unsigned* r, const void* p) {
    unsigned addr = (unsigned)__cvta_generic_to_shared(p);
    asm volatile("ldmatrix.sync.aligned.m8n8.x4.shared.b16 {%0,%1,%2,%3}, [%4];"
        : "=r"(r[0]), "=r"(r[1]), "=r"(r[2]), "=r"(r[3]) : "r"(addr));
}
__device__ __forceinline__ void ldsm_x4_t(unsigned* r, const void* p) {
    unsigned addr = (unsigned)__cvta_generic_to_shared(p);
    asm volatile("ldmatrix.sync.aligned.m8n8.x4.trans.shared.b16 {%0,%1,%2,%3}, [%4];"
        : "=r"(r[0]), "=r"(r[1]), "=r"(r[2]), "=r"(r[3]) : "r"(addr));
}
__device__ __forceinline__ void mma_f16(float* c, const unsigned* a, const unsigned* b) {
    asm volatile("mma.sync.aligned.m16n8k16.row.col.f32.f16.f16.f32 "
        "{%0,%1,%2,%3}, {%4,%5,%6,%7}, {%8,%9}, {%0,%1,%2,%3};"
        : "+f"(c[0]), "+f"(c[1]), "+f"(c[2]), "+f"(c[3])
        : "r"(a[0]), "r"(a[1]), "r"(a[2]), "r"(a[3]), "r"(b[0]), "r"(b[1]));
}
// fp16 hi/lo pair (attention Q only)
__device__ __forceinline__ void hilo_pair_f16(float x, float y, unsigned& h, unsigned& l) {
    __half hx = __float2half_rn(x), hy = __float2half_rn(y);
    float rx = x - __half2float(hx), ry = y - __half2float(hy);
    __half lx = __float2half_rn(rx), ly = __float2half_rn(ry);
    h = (unsigned)__half_as_ushort(hx) | ((unsigned)__half_as_ushort(hy) << 16);
    l = (unsigned)__half_as_ushort(lx) | ((unsigned)__half_as_ushort(ly) << 16);
}
__device__ __forceinline__ unsigned pkf16(float x, float y) {
    __half2 h = __floats2half2_rn(x, y);
    return *(unsigned*)&h;
}
__device__ __forceinline__ float ex2f(float x) {
    float y; asm("ex2.approx.ftz.f32 %0, %1;" : "=f"(y) : "f"(x)); return y;
}
// ---- cp.async ----
__device__ __forceinline__ void cp_async16(void* smem_dst, const void* gmem_src) {
    unsigned d = (unsigned)__cvta_generic_to_shared(smem_dst);
    asm volatile("cp.async.cg.shared.global [%0], [%1], 16;" :: "r"(d), "l"(gmem_src));
}
__device__ __forceinline__ void cp_commit() {
    asm volatile("cp.async.commit_group;" ::: "memory");
}
__device__ __forceinline__ void cp_wait0() {
    asm volatile("cp.async.wait_group 0;" ::: "memory");
}

// ---------------------------------------------------------------------------
// Kernel 0: convert x + 4 weights fp32 -> single fp16. Flat 1D grid sized
// exactly 4*nW + nX float4s (no dead blocks).
// ---------------------------------------------------------------------------
__global__ __launch_bounds__(256) void split_flat_kernel(
    const float* __restrict__ s0, const float* __restrict__ s1,
    const float* __restrict__ s2, const float* __restrict__ s3,
    const float* __restrict__ s4, int nW, int total4)
{
    int i = blockIdx.x * blockDim.x + threadIdx.x;
    if (i >= total4) return;
    const float* src;
    ushort_t* df;
    int j;
    if (i < 4 * nW) {
        int w = i / nW;
        j = i - w * nW;
        switch (w) {
            case 0: src = s0; df = g_Wqf; break;
            case 1: src = s1; df = g_Wkf; break;
            case 2: src = s2; df = g_Wvf; break;
            default: src = s3; df = g_Wof; break;
        }
    } else {
        j = i - 4 * nW;
        src = s4; df = g_xf;
    }
    float4 v = *(const float4*)(src + (size_t)j * 4);
    *(uint2*)(df + (size_t)j * 4) = make_uint2(pkf16(v.x, v.y), pkf16(v.z, v.w));
}

// ---------------------------------------------------------------------------
// Kernel 1: fused QKV projection (R14-proven, byte-identical).
// Pure fp16 GEMM, k-step 16, LDG->reg->STS double-buffered staging.
// ---------------------------------------------------------------------------
__global__ __launch_bounds__(256) void qkv_kernel(
    const float* __restrict__ bq, const float* __restrict__ bk,
    const float* __restrict__ bv)
{
    __shared__ ushort_t As_f[2][128][24];
    __shared__ ushort_t Bs_f[2][16][136];

    const int tid = threadIdx.x;
    const int lane = tid & 31;
    const int warp = tid >> 5;
    const int wm = warp & 1;
    const int wn = warp >> 1;
    const int m0 = blockIdx.x * 128;
    const int n0 = blockIdx.y * 128;
    const int z = n0 >> 10;
    const ushort_t* Wf = (z == 0 ? g_Wqf : (z == 1 ? g_Wkf : g_Wvf));
    const float* bias  = (z == 0 ? bq : (z == 1 ? bk : bv));

    const int arow = tid >> 1;
    const int apart = (tid & 1) * 8;
    const ushort_t* Ag = g_xf + (size_t)(m0 + arow) * Edim + apart;
    const int bkr = tid >> 4;
    const int bj = (tid & 15) * 8;
    const int cB = n0 + bj;
    const ushort_t* Bgf = Wf + (size_t)((cB >> 6) & 15) * (Edim * DHd) + (cB & 63);

    float C[4][4][4];
#pragma unroll
    for (int i = 0; i < 4; i++)
#pragma unroll
        for (int j = 0; j < 4; j++)
#pragma unroll
            for (int e = 0; e < 4; e++) C[i][j][e] = 0.f;

    uint4 aF, bF;
    aF = *(const uint4*)(Ag);
    bF = *(const uint4*)(Bgf + (size_t)bkr * DHd);
    *(uint4*)&As_f[0][arow][apart] = aF;
    *(uint4*)&Bs_f[0][bkr][bj] = bF;
    __syncthreads();

    const int lrow = lane & 15;
    const int lkoff = (lane >> 4) * 8;

    int buf = 0;
    for (int k0 = 0; k0 < Edim; k0 += 16) {
        const bool more = (k0 + 16) < Edim;
        if (more) {
            aF = *(const uint4*)(Ag + k0 + 16);
            bF = *(const uint4*)(Bgf + (size_t)(k0 + 16 + bkr) * DHd);
        }

        unsigned a_f[4][4], b_f[4][2];
#pragma unroll
        for (int mi = 0; mi < 4; mi++)
            ldsm_x4(a_f[mi], &As_f[buf][wm * 64 + mi * 16 + lrow][lkoff]);
#pragma unroll
        for (int np = 0; np < 2; np++) {
            unsigned r[4];
            ldsm_x4_t(r, &Bs_f[buf][lrow][wn * 32 + np * 16 + lkoff]);
            b_f[2*np][0] = r[0]; b_f[2*np][1] = r[1];
            b_f[2*np+1][0] = r[2]; b_f[2*np+1][1] = r[3];
        }
#pragma unroll
        for (int mi = 0; mi < 4; mi++)
#pragma unroll
            for (int ni = 0; ni < 4; ni++)
                mma_f16(C[mi][ni], a_f[mi], b_f[ni]);

        if (more) {
            int nb = buf ^ 1;
            *(uint4*)&As_f[nb][arow][apart] = aF;
            *(uint4*)&Bs_f[nb][bkr][bj] = bF;
        }
        __syncthreads();
        buf ^= 1;
    }

    // epilogue: Q fp32; K fp16; V fp16
#pragma unroll
    for (int mi = 0; mi < 4; mi++)
#pragma unroll
        for (int ni = 0; ni < 4; ni++) {
            int gm = m0 + wm * 64 + mi * 16 + (lane >> 2);
            int gc = n0 + wn * 32 + ni * 8 + (lane & 3) * 2;
            float b0f = bias[gc & 1023];
            float b1f = bias[(gc & 1023) + 1];
            int h = (gc >> 6) & 15;
            int d = gc & 63;
            int bb = gm >> 11, s = gm & (Sdim - 1);
            size_t off0 = ((size_t)(bb * Hn + h) * Sdim + s) * DHd + d;
            int gm2 = gm + 8;
            int bb2 = gm2 >> 11, s2 = gm2 & (Sdim - 1);
            size_t off1 = ((size_t)(bb2 * Hn + h) * Sdim + s2) * DHd + d;
            float v00 = C[mi][ni][0] + b0f, v01 = C[mi][ni][1] + b1f;
            float v10 = C[mi][ni][2] + b0f, v11 = C[mi][ni][3] + b1f;
            if (z == 0) {
                *(float2*)(g_Q + off0) = make_float2(v00, v01);
                *(float2*)(g_Q + off1) = make_float2(v10, v11);
            } else {
                ushort_t* dst = (z == 1 ? g_Kf : g_Vf);
                *(unsigned*)(dst + off0) = pkf16(v00, v01);
                *(unsigned*)(dst + off1) = pkf16(v10, v11);
            }
        }
}

// ---------------------------------------------------------------------------
// Kernel 2: flash attention, fp16 (R14-proven, byte-identical).
// ---------------------------------------------------------------------------
#define ATILE 4608            // 64*72 ushorts per array
#define ABUF  (2 * ATILE)
#define ATTN_SMEM_BYTES (2 * ABUF * 2)   // 36,864 B

__global__ __launch_bounds__(256) void attn_kernel()
{
    extern __shared__ ushort_t asmem[];

    const int bh = blockIdx.y;
    const int tid = threadIdx.x;
    const int lane = tid & 31;
    const int warp = tid >> 5;

    const float* Qp = g_Q + (size_t)bh * Sdim * DHd;
    const ushort_t* Kp = g_Kf + (size_t)bh * Sdim * DHd;
    const ushort_t* Vp = g_Vf + (size_t)bh * Sdim * DHd;

    const float SCALE = 0.125f * 1.4426950408889634f;

    unsigned aq_h[4][4], aq_l[4][4];
    {
        const int r0 = blockIdx.x * 128 + warp * 16 + (lane >> 2);
        const int r1 = r0 + 8;
        const int cb = (lane & 3) * 2;
#pragma unroll
        for (int kk = 0; kk < 4; kk++) {
            float2 v00 = *(const float2*)(Qp + (size_t)r0 * DHd + kk * 16 + cb);
            float2 v01 = *(const float2*)(Qp + (size_t)r0 * DHd + kk * 16 + cb + 8);
            float2 v10 = *(const float2*)(Qp + (size_t)r1 * DHd + kk * 16 + cb);
            float2 v11 = *(const float2*)(Qp + (size_t)r1 * DHd + kk * 16 + cb + 8);
            hilo_pair_f16(v00.x * SCALE, v00.y * SCALE, aq_h[kk][0], aq_l[kk][0]);
            hilo_pair_f16(v10.x * SCALE, v10.y * SCALE, aq_h[kk][1], aq_l[kk][1]);
            hilo_pair_f16(v01.x * SCALE, v01.y * SCALE, aq_h[kk][2], aq_l[kk][2]);
            hilo_pair_f16(v11.x * SCALE, v11.y * SCALE, aq_h[kk][3], aq_l[kk][3]);
        }
    }

    float o[8][4];
#pragma unroll
    for (int i = 0; i < 8; i++)
#pragma unroll
        for (int e = 0; e < 4; e++) o[i][e] = 0.f;
    float m0_ = -INFINITY, m1_ = -INFINITY, l0_ = 0.f, l1_ = 0.f;

    const int l15 = lane & 15;
    const int lk8 = (lane >> 4) * 8;
    const int srow = tid >> 3;
    const int sc8 = (tid & 7) * 8;

#pragma unroll
    for (int i = 0; i < 2; i++) {
        int row = srow + i * 32;
        size_t goff = (size_t)row * DHd + sc8;
        int soff = row * 72 + sc8;
        cp_async16(&asmem[0 * ABUF + 0 * ATILE + soff], Kp + goff);
        cp_async16(&asmem[0 * ABUF + 1 * ATILE + soff], Vp + goff);
    }
    cp_commit();

    int buf = 0;
    for (int t0 = 0; t0 < Sdim; t0 += 64) {
        cp_wait0();
        __syncthreads();

        const ushort_t* Ks = asmem + buf * ABUF + 0 * ATILE;
        const ushort_t* Vs = asmem + buf * ABUF + 1 * ATILE;

        if (t0 + 64 < Sdim) {
            int nb = buf ^ 1;
#pragma unroll
            for (int i = 0; i < 2; i++) {
                int row = srow + i * 32;
                size_t goff = (size_t)(t0 + 64 + row) * DHd + sc8;
                int soff = row * 72 + sc8;
                cp_async16(&asmem[nb * ABUF + 0 * ATILE + soff], Kp + goff);
                cp_async16(&asmem[nb * ABUF + 1 * ATILE + soff], Vp + goff);
            }
            cp_commit();
        }

        float sc[8][4];
#pragma unroll
        for (int i = 0; i < 8; i++)
#pragma unroll
            for (int e = 0; e < 4; e++) sc[i][e] = 0.f;

#pragma unroll
        for (int kk = 0; kk < 4; kk++) {
#pragma unroll
            for (int pp = 0; pp < 4; pp++) {
                unsigned rk[4];
                ldsm_x4(rk, &Ks[(pp * 16 + l15) * 72 + kk * 16 + lk8]);
                unsigned bk0[2] = {rk[0], rk[2]}, bk1[2] = {rk[1], rk[3]};
                mma_f16(sc[2*pp],   aq_h[kk], bk0);
                mma_f16(sc[2*pp],   aq_l[kk], bk0);
                mma_f16(sc[2*pp+1], aq_h[kk], bk1);
                mma_f16(sc[2*pp+1], aq_l[kk], bk1);
            }
        }

        float mx0 = m0_, mx1 = m1_;
#pragma unroll
        for (int i = 0; i < 8; i++) {
            mx0 = fmaxf(mx0, fmaxf(sc[i][0], sc[i][1]));
            mx1 = fmaxf(mx1, fmaxf(sc[i][2], sc[i][3]));
        }
        mx0 = fmaxf(mx0, __shfl_xor_sync(0xffffffffu, mx0, 1));
        mx0 = fmaxf(mx0, __shfl_xor_sync(0xffffffffu, mx0, 2));
        mx1 = fmaxf(mx1, __shfl_xor_sync(0xffffffffu, mx1, 1));
        mx1 = fmaxf(mx1, __shfl_xor_sync(0xffffffffu, mx1, 2));
        if (mx0 > m0_) {
            float corr = ex2f(m0_ - mx0);
            m0_ = mx0; l0_ *= corr;
#pragma unroll
            for (int i = 0; i < 8; i++) { o[i][0] *= corr; o[i][1] *= corr; }
        }
        if (mx1 > m1_) {
            float corr = ex2f(m1_ - mx1);
            m1_ = mx1; l1_ *= corr;
#pragma unroll
            for (int i = 0; i < 8; i++) { o[i][2] *= corr; o[i][3] *= corr; }
        }
        float ts0 = 0.f, ts1 = 0.f;
#pragma unroll
        for (int i = 0; i < 8; i++) {
            sc[i][0] = ex2f(sc[i][0] - m0_);
            sc[i][1] = ex2f(sc[i][1] - m0_);
            sc[i][2] = ex2f(sc[i][2] - m1_);
            sc[i][3] = ex2f(sc[i][3] - m1_);
            ts0 += sc[i][0] + sc[i][1];
            ts1 += sc[i][2] + sc[i][3];
        }
        ts0 += __shfl_xor_sync(0xffffffffu, ts0, 1);
        ts0 += __shfl_xor_sync(0xffffffffu, ts0, 2);
        ts1 += __shfl_xor_sync(0xffffffffu, ts1, 1);
        ts1 += __shfl_xor_sync(0xffffffffu, ts1, 2);
        l0_ += ts0; l1_ += ts1;

        // --- O += P @ V: both single fp16 ---
#pragma unroll
        for (int ss = 0; ss < 4; ss++) {
            unsigned ap[4];
            ap[0] = pkf16(sc[2*ss][0],   sc[2*ss][1]);
            ap[1] = pkf16(sc[2*ss][2],   sc[2*ss][3]);
            ap[2] = pkf16(sc[2*ss+1][0], sc[2*ss+1][1]);
            ap[3] = pkf16(sc[2*ss+1][2], sc[2*ss+1][3]);
#pragma unroll
            for (int np = 0; np < 4; np++) {
                unsigned vv[4];
                ldsm_x4_t(vv, &Vs[(ss * 16 + l15) * 72 + np * 16 + lk8]);
                unsigned b0[2] = {vv[0], vv[1]}, b1[2] = {vv[2], vv[3]};
                mma_f16(o[2*np],   ap, b0);
                mma_f16(o[2*np+1], ap, b1);
            }
        }
        __syncthreads();
        buf ^= 1;
    }

    // write normalized O as fp16 to g_Of
    const float inv0 = 1.0f / l0_, inv1 = 1.0f / l1_;
    const int b = bh >> 4, h = bh & 15;
    const int r0 = blockIdx.x * 128 + warp * 16 + (lane >> 2);
    size_t base0 = (size_t)(b * Sdim + r0) * Adim + h * DHd;
    size_t base1 = (size_t)(b * Sdim + r0 + 8) * Adim + h * DHd;
#pragma unroll
    for (int np = 0; np < 8; np++) {
        int col = np * 8 + (lane & 3) * 2;
        *(unsigned*)(g_Of + base0 + col) = pkf16(o[np][0] * inv0, o[np][1] * inv0);
        *(unsigned*)(g_Of + base1 + col) = pkf16(o[np][2] * inv1, o[np][3] * inv1);
    }
}

// ---------------------------------------------------------------------------
// Kernel 3: output projection, fp16 GEMM, k-step 32 with LDG->reg->STS
// prefetch (isolated k-step experiment; R14 schedule otherwise).
// ---------------------------------------------------------------------------
__global__ __launch_bounds__(256) void outproj_kernel(
    const float* __restrict__ bo, float* __restrict__ out)
{
    __shared__ __align__(16) ushort_t As_f[2][128][40];  // [buf][m][32k + 8 pad]
    __shared__ __align__(16) ushort_t Bs_f[2][32][136];  // [buf][k][128n + 8 pad]

    const int tid = threadIdx.x;
    const int lane = tid & 31;
    const int warp = tid >> 5;
    const int wm = warp & 1;
    const int wn = warp >> 1;
    const int m0 = blockIdx.x * 128;
    const int n0 = blockIdx.y * 128;

    // A chunks: c = tid + 256*j -> row = c>>2 (0..127), kc = (c&3)*8
    const int a0row = tid >> 2,          a0kc = (tid & 3) * 8;
    const int a1row = (tid + 256) >> 2,  a1kc = ((tid + 256) & 3) * 8;
    const ushort_t* Ag0 = g_Of + (size_t)(m0 + a0row) * Adim + a0kc;
    const ushort_t* Ag1 = g_Of + (size_t)(m0 + a1row) * Adim + a1kc;
    // B chunks: c = tid + 256*j -> krow = c>>4 (0..31), nc = (c&15)*8
    const int b0k = tid >> 4,            b0n = (tid & 15) * 8;
    const int b1k = (tid + 256) >> 4,    b1n = ((tid + 256) & 15) * 8;
    const ushort_t* Bg0 = g_Wof + n0 + b0n;
    const ushort_t* Bg1 = g_Wof + n0 + b1n;

    float C[4][4][4];
#pragma unroll
    for (int i = 0; i < 4; i++)
#pragma unroll
        for (int j = 0; j < 4; j++)
#pragma unroll
            for (int e = 0; e < 4; e++) C[i][j][e] = 0.f;

    // preload tile 0 into buffer 0 (LDG -> regs -> STS, R14 schedule)
    uint4 a0F, a1F, b0F, b1F;
    a0F = *(const uint4*)(Ag0);
    a1F = *(const uint4*)(Ag1);
    b0F = *(const uint4*)(Bg0 + (size_t)b0k * Edim);
    b1F = *(const uint4*)(Bg1 + (size_t)b1k * Edim);
    *(uint4*)&As_f[0][a0row][a0kc] = a0F;
    *(uint4*)&As_f[0][a1row][a1kc] = a1F;
    *(uint4*)&Bs_f[0][b0k][b0n] = b0F;
    *(uint4*)&Bs_f[0][b1k][b1n] = b1F;
    __syncthreads();

    const int lrow = lane & 15;
    const int lk8 = (lane >> 4) * 8;

    int buf = 0;
    for (int k0 = 0; k0 < Adim; k0 += 32) {
        const bool more = (k0 + 32) < Adim;
        if (more) {
            a0F = *(const uint4*)(Ag0 + k0 + 32);
            a1F = *(const uint4*)(Ag1 + k0 + 32);
            b0F = *(const uint4*)(Bg0 + (size_t)(k0 + 32 + b0k) * Edim);
            b1F = *(const uint4*)(Bg1 + (size_t)(k0 + 32 + b1k) * Edim);
        }

#pragma unroll
        for (int kh = 0; kh < 2; kh++) {
            unsigned a_f[4][4], b_f[4][2];
#pragma unroll
            for (int mi = 0; mi < 4; mi++)
                ldsm_x4(a_f[mi], &As_f[buf][wm * 64 + mi * 16 + lrow][kh * 16 + lk8]);
#pragma unroll
            for (int np = 0; np < 2; np++) {
                unsigned r[4];
                ldsm_x4_t(r, &Bs_f[buf][kh * 16 + lrow][wn * 32 + np * 16 + lk8]);
                b_f[2*np][0] = r[0]; b_f[2*np][1] = r[1];
                b_f[2*np+1][0] = r[2]; b_f[2*np+1][1] = r[3];
            }
#pragma unroll
            for (int mi = 0; mi < 4; mi++)
#pragma unroll
                for (int ni = 0; ni < 4; ni++)
                    mma_f16(C[mi][ni], a_f[mi], b_f[ni]);
        }

        if (more) {
            int nb = buf ^ 1;
            *(uint4*)&As_f[nb][a0row][a0kc] = a0F;
            *(uint4*)&As_f[nb][a1row][a1kc] = a1F;
            *(uint4*)&Bs_f[nb][b0k][b0n] = b0F;
            *(uint4*)&Bs_f[nb][b1k][b1n] = b1F;
        }
        __syncthreads();
        buf ^= 1;
    }

#pragma unroll
    for (int mi = 0; mi < 4; mi++)
#pragma unroll
        for (int ni = 0; ni < 4; ni++) {
            int gm = m0 + wm * 64 + mi * 16 + (lane >> 2);
            int gc = n0 + wn * 32 + ni * 8 + (lane & 3) * 2;
            float b0f = bo[gc], b1f = bo[gc + 1];
            float* p0 = out + (size_t)gm * Edim + gc;
            *(float2*)p0 = make_float2(C[mi][ni][0] + b0f, C[mi][ni][1] + b1f);
            float* p1 = out + (size_t)(gm + 8) * Edim + gc;
            *(float2*)p1 = make_float2(C[mi][ni][2] + b0f, C[mi][ni][3] + b1f);
        }
}

extern "C" void kernel_launch(void* const* d_in, const int* in_sizes, int n_in,
                              void* d_out, int out_size)
{
    const float* x  = (const float*)d_in[0];
    const float* Wq = (const float*)d_in[1];
    const float* bq = (const float*)d_in[2];
    const float* Wk = (const float*)d_in[3];
    const float* bk = (const float*)d_in[4];
    const float* Wv = (const float*)d_in[5];
    const float* bv = (const float*)d_in[6];
    const float* Wo = (const float*)d_in[7];
    const float* bo = (const float*)d_in[8];
    float* out = (float*)d_out;

    static bool attr_set = false;
    if (!attr_set) {
        cudaFuncSetAttribute(attn_kernel,
            cudaFuncAttributeMaxDynamicSharedMemorySize, ATTN_SMEM_BYTES);
        attr_set = true;
    }

    const int nW = Hn * Edim * DHd / 4;           // 262,144 float4s per weight
    const int nX = Mrows * Edim / 4;              // 1,048,576 float4s
    const int total4 = 4 * nW + nX;               // 2,097,152
    split_flat_kernel<<<(total4 + 255) / 256, 256>>>(Wq, Wk, Wv, Wo, x, nW, total4);

    dim3 g1(Mrows / 128, (3 * Hn * DHd) / 128);   // (32, 24)
    qkv_kernel<<<g1, 256>>>(bq, bk, bv);

    dim3 g2(Sdim / 128, Bsz * Hn);                // (16, 32)
    attn_kernel<<<g2, 256, ATTN_SMEM_BYTES>>>();

    dim3 g3(Mrows / 128, Edim / 128);             // (32, 8)
    outproj_kernel<<<g3, 256>>>(bo, out);
}

// round 17
// speedup vs baseline: 1.5502x; 1.0583x over previous
#include <cuda_runtime.h>
#include <cuda_bf16.h>
#include <cuda_fp16.h>
#include <math.h>

#define Bsz 2
#define Sdim 2048
#define Edim 1024
#define Hn 16
#define DHd 64
#define Adim 1024
#define Mrows (Bsz * Sdim)  // 4096

typedef unsigned short ushort_t;

// Scratch (allocation-free rule: __device__ globals)
__device__ __align__(256) float    g_Q [(size_t)Bsz * Hn * Sdim * DHd];  // [B,H,S,DH] fp32
__device__ __align__(256) ushort_t g_Kf[(size_t)Bsz * Hn * Sdim * DHd];  // K fp16
__device__ __align__(256) ushort_t g_Vf[(size_t)Bsz * Hn * Sdim * DHd];  // V fp16
__device__ __align__(256) ushort_t g_Of[(size_t)Bsz * Sdim * Adim];      // attn out fp16
// pre-converted inputs (single fp16)
__device__ __align__(256) ushort_t g_xf [(size_t)Mrows * Edim];
__device__ __align__(256) ushort_t g_Wqf[(size_t)Hn * Edim * DHd];
__device__ __align__(256) ushort_t g_Wkf[(size_t)Hn * Edim * DHd];
__device__ __align__(256) ushort_t g_Wvf[(size_t)Hn * Edim * DHd];
__device__ __align__(256) ushort_t g_Wof[(size_t)Adim * Edim];

// ---- mma.sync helpers --------------------------------------------------
__device__ __forceinline__ void ldsm_x4(unsigned* r, const void* p) {
    unsigned addr = (unsigned)__cvta_generic_to_shared(p);
    asm volatile("ldmatrix.sync.aligned.m8n8.x4.shared.b16 {%0,%1,%2,%3}, [%4];"
        : "=r"(r[0]), "=r"(r[1]), "=r"(r[2]), "=r"(r[3]) : "r"(addr));
}
__device__ __forceinline__ void ldsm_x4_t(unsigned* r, const void* p) {
    unsigned addr = (unsigned)__cvta_generic_to_shared(p);
    asm volatile("ldmatrix.sync.aligned.m8n8.x4.trans.shared.b16 {%0,%1,%2,%3}, [%4];"
        : "=r"(r[0]), "=r"(r[1]), "=r"(r[2]), "=r"(r[3]) : "r"(addr));
}
__device__ __forceinline__ void mma_f16(float* c, const unsigned* a, const unsigned* b) {
    asm volatile("mma.sync.aligned.m16n8k16.row.col.f32.f16.f16.f32 "
        "{%0,%1,%2,%3}, {%4,%5,%6,%7}, {%8,%9}, {%0,%1,%2,%3};"
        : "+f"(c[0]), "+f"(c[1]), "+f"(c[2]), "+f"(c[3])
        : "r"(a[0]), "r"(a[1]), "r"(a[2]), "r"(a[3]), "r"(b[0]), "r"(b[1]));
}
// fp16 hi/lo pair (attention Q only)
__device__ __forceinline__ void hilo_pair_f16(float x, float y, unsigned& h, unsigned& l) {
    __half hx = __float2half_rn(x), hy = __float2half_rn(y);
    float rx = x - __half2float(hx), ry = y - __half2float(hy);
    __half lx = __float2half_rn(rx), ly = __float2half_rn(ry);
    h = (unsigned)__half_as_ushort(hx) | ((unsigned)__half_as_ushort(hy) << 16);
    l = (unsigned)__half_as_ushort(lx) | ((unsigned)__half_as_ushort(ly) << 16);
}
__device__ __forceinline__ unsigned pkf16(float x, float y) {
    __half2 h = __floats2half2_rn(x, y);
    return *(unsigned*)&h;
}
__device__ __forceinline__ float ex2f(float x) {
    float y; asm("ex2.approx.ftz.f32 %0, %1;" : "=f"(y) : "f"(x)); return y;
}
// ---- cp.async (attention staging only) ----
__device__ __forceinline__ void cp_async16(void* smem_dst, const void* gmem_src) {
    unsigned d = (unsigned)__cvta_generic_to_shared(smem_dst);
    asm volatile("cp.async.cg.shared.global [%0], [%1], 16;" :: "r"(d), "l"(gmem_src));
}
__device__ __forceinline__ void cp_commit() {
    asm volatile("cp.async.commit_group;" ::: "memory");
}
__device__ __forceinline__ void cp_wait0() {
    asm volatile("cp.async.wait_group 0;" ::: "memory");
}

// ---------------------------------------------------------------------------
// Kernel 0: convert x + 4 weights fp32 -> single fp16. Flat 1D grid.
// ---------------------------------------------------------------------------
__global__ __launch_bounds__(256) void split_flat_kernel(
    const float* __restrict__ s0, const float* __restrict__ s1,
    const float* __restrict__ s2, const float* __restrict__ s3,
    const float* __restrict__ s4, int nW, int total4)
{
    int i = blockIdx.x * blockDim.x + threadIdx.x;
    if (i >= total4) return;
    const float* src;
    ushort_t* df;
    int j;
    if (i < 4 * nW) {
        int w = i / nW;
        j = i - w * nW;
        switch (w) {
            case 0: src = s0; df = g_Wqf; break;
            case 1: src = s1; df = g_Wkf; break;
            case 2: src = s2; df = g_Wvf; break;
            default: src = s3; df = g_Wof; break;
        }
    } else {
        j = i - 4 * nW;
        src = s4; df = g_xf;
    }
    float4 v = *(const float4*)(src + (size_t)j * 4);
    *(uint2*)(df + (size_t)j * 4) = make_uint2(pkf16(v.x, v.y), pkf16(v.z, v.w));
}

// ---------------------------------------------------------------------------
// Kernel 1: fused QKV projection, fp16 GEMM, k-step 32 with LDG->reg->STS
// prefetch (R16-outproj-proven schedule). Epilogue: Q fp32, K/V fp16.
// ---------------------------------------------------------------------------
__global__ __launch_bounds__(256) void qkv_kernel(
    const float* __restrict__ bq, const float* __restrict__ bk,
    const float* __restrict__ bv)
{
    __shared__ __align__(16) ushort_t As_f[2][128][40];  // [buf][m][32k + 8 pad]
    __shared__ __align__(16) ushort_t Bs_f[2][32][136];  // [buf][k][128n + 8 pad]

    const int tid = threadIdx.x;
    const int lane = tid & 31;
    const int warp = tid >> 5;
    const int wm = warp & 1;
    const int wn = warp >> 1;
    const int m0 = blockIdx.x * 128;
    const int n0 = blockIdx.y * 128;
    const int z = n0 >> 10;
    const ushort_t* Wf = (z == 0 ? g_Wqf : (z == 1 ? g_Wkf : g_Wvf));
    const float* bias  = (z == 0 ? bq : (z == 1 ? bk : bv));

    // A chunks: c = tid + 256*j -> row = c>>2 (0..127), kc = (c&3)*8
    const int a0row = tid >> 2,          a0kc = (tid & 3) * 8;
    const int a1row = (tid + 256) >> 2,  a1kc = ((tid + 256) & 3) * 8;
    const ushort_t* Ag0 = g_xf + (size_t)(m0 + a0row) * Edim + a0kc;
    const ushort_t* Ag1 = g_xf + (size_t)(m0 + a1row) * Edim + a1kc;
    // B chunks: c = tid + 256*j -> krow = c>>4 (0..31), nc = (c&15)*8
    // head-strided addressing: 8-wide chunk never crosses a 64-wide head
    const int b0k = tid >> 4,            b0n = (tid & 15) * 8;
    const int b1k = (tid + 256) >> 4,    b1n = ((tid + 256) & 15) * 8;
    const int cB0 = n0 + b0n, cB1 = n0 + b1n;
    const ushort_t* Bg0 = Wf + (size_t)((cB0 >> 6) & 15) * (Edim * DHd) + (cB0 & 63);
    const ushort_t* Bg1 = Wf + (size_t)((cB1 >> 6) & 15) * (Edim * DHd) + (cB1 & 63);

    float C[4][4][4];
#pragma unroll
    for (int i = 0; i < 4; i++)
#pragma unroll
        for (int j = 0; j < 4; j++)
#pragma unroll
            for (int e = 0; e < 4; e++) C[i][j][e] = 0.f;

    // preload tile 0 into buffer 0 (LDG -> regs -> STS)
    uint4 a0F, a1F, b0F, b1F;
    a0F = *(const uint4*)(Ag0);
    a1F = *(const uint4*)(Ag1);
    b0F = *(const uint4*)(Bg0 + (size_t)b0k * DHd);
    b1F = *(const uint4*)(Bg1 + (size_t)b1k * DHd);
    *(uint4*)&As_f[0][a0row][a0kc] = a0F;
    *(uint4*)&As_f[0][a1row][a1kc] = a1F;
    *(uint4*)&Bs_f[0][b0k][b0n] = b0F;
    *(uint4*)&Bs_f[0][b1k][b1n] = b1F;
    __syncthreads();

    const int lrow = lane & 15;
    const int lk8 = (lane >> 4) * 8;

    int buf = 0;
    for (int k0 = 0; k0 < Edim; k0 += 32) {
        const bool more = (k0 + 32) < Edim;
        if (more) {
            a0F = *(const uint4*)(Ag0 + k0 + 32);
            a1F = *(const uint4*)(Ag1 + k0 + 32);
            b0F = *(const uint4*)(Bg0 + (size_t)(k0 + 32 + b0k) * DHd);
            b1F = *(const uint4*)(Bg1 + (size_t)(k0 + 32 + b1k) * DHd);
        }

#pragma unroll
        for (int kh = 0; kh < 2; kh++) {
            unsigned a_f[4][4], b_f[4][2];
#pragma unroll
            for (int mi = 0; mi < 4; mi++)
                ldsm_x4(a_f[mi], &As_f[buf][wm * 64 + mi * 16 + lrow][kh * 16 + lk8]);
#pragma unroll
            for (int np = 0; np < 2; np++) {
                unsigned r[4];
                ldsm_x4_t(r, &Bs_f[buf][kh * 16 + lrow][wn * 32 + np * 16 + lk8]);
                b_f[2*np][0] = r[0]; b_f[2*np][1] = r[1];
                b_f[2*np+1][0] = r[2]; b_f[2*np+1][1] = r[3];
            }
#pragma unroll
            for (int mi = 0; mi < 4; mi++)
#pragma unroll
                for (int ni = 0; ni < 4; ni++)
                    mma_f16(C[mi][ni], a_f[mi], b_f[ni]);
        }

        if (more) {
            int nb = buf ^ 1;
            *(uint4*)&As_f[nb][a0row][a0kc] = a0F;
            *(uint4*)&As_f[nb][a1row][a1kc] = a1F;
            *(uint4*)&Bs_f[nb][b0k][b0n] = b0F;
            *(uint4*)&Bs_f[nb][b1k][b1n] = b1F;
        }
        __syncthreads();
        buf ^= 1;
    }

    // epilogue: Q fp32; K fp16; V fp16
#pragma unroll
    for (int mi = 0; mi < 4; mi++)
#pragma unroll
        for (int ni = 0; ni < 4; ni++) {
            int gm = m0 + wm * 64 + mi * 16 + (lane >> 2);
            int gc = n0 + wn * 32 + ni * 8 + (lane & 3) * 2;
            float b0f = bias[gc & 1023];
            float b1f = bias[(gc & 1023) + 1];
            int h = (gc >> 6) & 15;
            int d = gc & 63;
            int bb = gm >> 11, s = gm & (Sdim - 1);
            size_t off0 = ((size_t)(bb * Hn + h) * Sdim + s) * DHd + d;
            int gm2 = gm + 8;
            int bb2 = gm2 >> 11, s2 = gm2 & (Sdim - 1);
            size_t off1 = ((size_t)(bb2 * Hn + h) * Sdim + s2) * DHd + d;
            float v00 = C[mi][ni][0] + b0f, v01 = C[mi][ni][1] + b1f;
            float v10 = C[mi][ni][2] + b0f, v11 = C[mi][ni][3] + b1f;
            if (z == 0) {
                *(float2*)(g_Q + off0) = make_float2(v00, v01);
                *(float2*)(g_Q + off1) = make_float2(v10, v11);
            } else {
                ushort_t* dst = (z == 1 ? g_Kf : g_Vf);
                *(unsigned*)(dst + off0) = pkf16(v00, v01);
                *(unsigned*)(dst + off1) = pkf16(v10, v11);
            }
        }
}

// ---------------------------------------------------------------------------
// Kernel 2: flash attention, fp16 (R14-proven, byte-identical).
// ---------------------------------------------------------------------------
#define ATILE 4608            // 64*72 ushorts per array
#define ABUF  (2 * ATILE)
#define ATTN_SMEM_BYTES (2 * ABUF * 2)   // 36,864 B

__global__ __launch_bounds__(256) void attn_kernel()
{
    extern __shared__ ushort_t asmem[];

    const int bh = blockIdx.y;
    const int tid = threadIdx.x;
    const int lane = tid & 31;
    const int warp = tid >> 5;

    const float* Qp = g_Q + (size_t)bh * Sdim * DHd;
    const ushort_t* Kp = g_Kf + (size_t)bh * Sdim * DHd;
    const ushort_t* Vp = g_Vf + (size_t)bh * Sdim * DHd;

    const float SCALE = 0.125f * 1.4426950408889634f;

    unsigned aq_h[4][4], aq_l[4][4];
    {
        const int r0 = blockIdx.x * 128 + warp * 16 + (lane >> 2);
        const int r1 = r0 + 8;
        const int cb = (lane & 3) * 2;
#pragma unroll
        for (int kk = 0; kk < 4; kk++) {
            float2 v00 = *(const float2*)(Qp + (size_t)r0 * DHd + kk * 16 + cb);
            float2 v01 = *(const float2*)(Qp + (size_t)r0 * DHd + kk * 16 + cb + 8);
            float2 v10 = *(const float2*)(Qp + (size_t)r1 * DHd + kk * 16 + cb);
            float2 v11 = *(const float2*)(Qp + (size_t)r1 * DHd + kk * 16 + cb + 8);
            hilo_pair_f16(v00.x * SCALE, v00.y * SCALE, aq_h[kk][0], aq_l[kk][0]);
            hilo_pair_f16(v10.x * SCALE, v10.y * SCALE, aq_h[kk][1], aq_l[kk][1]);
            hilo_pair_f16(v01.x * SCALE, v01.y * SCALE, aq_h[kk][2], aq_l[kk][2]);
            hilo_pair_f16(v11.x * SCALE, v11.y * SCALE, aq_h[kk][3], aq_l[kk][3]);
        }
    }

    float o[8][4];
#pragma unroll
    for (int i = 0; i < 8; i++)
#pragma unroll
        for (int e = 0; e < 4; e++) o[i][e] = 0.f;
    float m0_ = -INFINITY, m1_ = -INFINITY, l0_ = 0.f, l1_ = 0.f;

    const int l15 = lane & 15;
    const int lk8 = (lane >> 4) * 8;
    const int srow = tid >> 3;
    const int sc8 = (tid & 7) * 8;

#pragma unroll
    for (int i = 0; i < 2; i++) {
        int row = srow + i * 32;
        size_t goff = (size_t)row * DHd + sc8;
        int soff = row * 72 + sc8;
        cp_async16(&asmem[0 * ABUF + 0 * ATILE + soff], Kp + goff);
        cp_async16(&asmem[0 * ABUF + 1 * ATILE + soff], Vp + goff);
    }
    cp_commit();

    int buf = 0;
    for (int t0 = 0; t0 < Sdim; t0 += 64) {
        cp_wait0();
        __syncthreads();

        const ushort_t* Ks = asmem + buf * ABUF + 0 * ATILE;
        const ushort_t* Vs = asmem + buf * ABUF + 1 * ATILE;

        if (t0 + 64 < Sdim) {
            int nb = buf ^ 1;
#pragma unroll
            for (int i = 0; i < 2; i++) {
                int row = srow + i * 32;
                size_t goff = (size_t)(t0 + 64 + row) * DHd + sc8;
                int soff = row * 72 + sc8;
                cp_async16(&asmem[nb * ABUF + 0 * ATILE + soff], Kp + goff);
                cp_async16(&asmem[nb * ABUF + 1 * ATILE + soff], Vp + goff);
            }
            cp_commit();
        }

        float sc[8][4];
#pragma unroll
        for (int i = 0; i < 8; i++)
#pragma unroll
            for (int e = 0; e < 4; e++) sc[i][e] = 0.f;

#pragma unroll
        for (int kk = 0; kk < 4; kk++) {
#pragma unroll
            for (int pp = 0; pp < 4; pp++) {
                unsigned rk[4];
                ldsm_x4(rk, &Ks[(pp * 16 + l15) * 72 + kk * 16 + lk8]);
                unsigned bk0[2] = {rk[0], rk[2]}, bk1[2] = {rk[1], rk[3]};
                mma_f16(sc[2*pp],   aq_h[kk], bk0);
                mma_f16(sc[2*pp],   aq_l[kk], bk0);
                mma_f16(sc[2*pp+1], aq_h[kk], bk1);
                mma_f16(sc[2*pp+1], aq_l[kk], bk1);
            }
        }

        float mx0 = m0_, mx1 = m1_;
#pragma unroll
        for (int i = 0; i < 8; i++) {
            mx0 = fmaxf(mx0, fmaxf(sc[i][0], sc[i][1]));
            mx1 = fmaxf(mx1, fmaxf(sc[i][2], sc[i][3]));
        }
        mx0 = fmaxf(mx0, __shfl_xor_sync(0xffffffffu, mx0, 1));
        mx0 = fmaxf(mx0, __shfl_xor_sync(0xffffffffu, mx0, 2));
        mx1 = fmaxf(mx1, __shfl_xor_sync(0xffffffffu, mx1, 1));
        mx1 = fmaxf(mx1, __shfl_xor_sync(0xffffffffu, mx1, 2));
        if (mx0 > m0_) {
            float corr = ex2f(m0_ - mx0);
            m0_ = mx0; l0_ *= corr;
#pragma unroll
            for (int i = 0; i < 8; i++) { o[i][0] *= corr; o[i][1] *= corr; }
        }
        if (mx1 > m1_) {
            float corr = ex2f(m1_ - mx1);
            m1_ = mx1; l1_ *= corr;
#pragma unroll
            for (int i = 0; i < 8; i++) { o[i][2] *= corr; o[i][3] *= corr; }
        }
        float ts0 = 0.f, ts1 = 0.f;
#pragma unroll
        for (int i = 0; i < 8; i++) {
            sc[i][0] = ex2f(sc[i][0] - m0_);
            sc[i][1] = ex2f(sc[i][1] - m0_);
            sc[i][2] = ex2f(sc[i][2] - m1_);
            sc[i][3] = ex2f(sc[i][3] - m1_);
            ts0 += sc[i][0] + sc[i][1];
            ts1 += sc[i][2] + sc[i][3];
        }
        ts0 += __shfl_xor_sync(0xffffffffu, ts0, 1);
        ts0 += __shfl_xor_sync(0xffffffffu, ts0, 2);
        ts1 += __shfl_xor_sync(0xffffffffu, ts1, 1);
        ts1 += __shfl_xor_sync(0xffffffffu, ts1, 2);
        l0_ += ts0; l1_ += ts1;

        // --- O += P @ V: both single fp16 ---
#pragma unroll
        for (int ss = 0; ss < 4; ss++) {
            unsigned ap[4];
            ap[0] = pkf16(sc[2*ss][0],   sc[2*ss][1]);
            ap[1] = pkf16(sc[2*ss][2],   sc[2*ss][3]);
            ap[2] = pkf16(sc[2*ss+1][0], sc[2*ss+1][1]);
            ap[3] = pkf16(sc[2*ss+1][2], sc[2*ss+1][3]);
#pragma unroll
            for (int np = 0; np < 4; np++) {
                unsigned vv[4];
                ldsm_x4_t(vv, &Vs[(ss * 16 + l15) * 72 + np * 16 + lk8]);
                unsigned b0[2] = {vv[0], vv[1]}, b1[2] = {vv[2], vv[3]};
                mma_f16(o[2*np],   ap, b0);
                mma_f16(o[2*np+1], ap, b1);
            }
        }
        __syncthreads();
        buf ^= 1;
    }

    // write normalized O as fp16 to g_Of
    const float inv0 = 1.0f / l0_, inv1 = 1.0f / l1_;
    const int b = bh >> 4, h = bh & 15;
    const int r0 = blockIdx.x * 128 + warp * 16 + (lane >> 2);
    size_t base0 = (size_t)(b * Sdim + r0) * Adim + h * DHd;
    size_t base1 = (size_t)(b * Sdim + r0 + 8) * Adim + h * DHd;
#pragma unroll
    for (int np = 0; np < 8; np++) {
        int col = np * 8 + (lane & 3) * 2;
        *(unsigned*)(g_Of + base0 + col) = pkf16(o[np][0] * inv0, o[np][1] * inv0);
        *(unsigned*)(g_Of + base1 + col) = pkf16(o[np][2] * inv1, o[np][3] * inv1);
    }
}

// ---------------------------------------------------------------------------
// Kernel 3: output projection (R16-proven, byte-identical).
// fp16 GEMM, k-step 32 with LDG->reg->STS prefetch.
// ---------------------------------------------------------------------------
__global__ __launch_bounds__(256) void outproj_kernel(
    const float* __restrict__ bo, float* __restrict__ out)
{
    __shared__ __align__(16) ushort_t As_f[2][128][40];
    __shared__ __align__(16) ushort_t Bs_f[2][32][136];

    const int tid = threadIdx.x;
    const int lane = tid & 31;
    const int warp = tid >> 5;
    const int wm = warp & 1;
    const int wn = warp >> 1;
    const int m0 = blockIdx.x * 128;
    const int n0 = blockIdx.y * 128;

    const int a0row = tid >> 2,          a0kc = (tid & 3) * 8;
    const int a1row = (tid + 256) >> 2,  a1kc = ((tid + 256) & 3) * 8;
    const ushort_t* Ag0 = g_Of + (size_t)(m0 + a0row) * Adim + a0kc;
    const ushort_t* Ag1 = g_Of + (size_t)(m0 + a1row) * Adim + a1kc;
    const int b0k = tid >> 4,            b0n = (tid & 15) * 8;
    const int b1k = (tid + 256) >> 4,    b1n = ((tid + 256) & 15) * 8;
    const ushort_t* Bg0 = g_Wof + n0 + b0n;
    const ushort_t* Bg1 = g_Wof + n0 + b1n;

    float C[4][4][4];
#pragma unroll
    for (int i = 0; i < 4; i++)
#pragma unroll
        for (int j = 0; j < 4; j++)
#pragma unroll
            for (int e = 0; e < 4; e++) C[i][j][e] = 0.f;

    uint4 a0F, a1F, b0F, b1F;
    a0F = *(const uint4*)(Ag0);
    a1F = *(const uint4*)(Ag1);
    b0F = *(const uint4*)(Bg0 + (size_t)b0k * Edim);
    b1F = *(const uint4*)(Bg1 + (size_t)b1k * Edim);
    *(uint4*)&As_f[0][a0row][a0kc] = a0F;
    *(uint4*)&As_f[0][a1row][a1kc] = a1F;
    *(uint4*)&Bs_f[0][b0k][b0n] = b0F;
    *(uint4*)&Bs_f[0][b1k][b1n] = b1F;
    __syncthreads();

    const int lrow = lane & 15;
    const int lk8 = (lane >> 4) * 8;

    int buf = 0;
    for (int k0 = 0; k0 < Adim; k0 += 32) {
        const bool more = (k0 + 32) < Adim;
        if (more) {
            a0F = *(const uint4*)(Ag0 + k0 + 32);
            a1F = *(const uint4*)(Ag1 + k0 + 32);
            b0F = *(const uint4*)(Bg0 + (size_t)(k0 + 32 + b0k) * Edim);
            b1F = *(const uint4*)(Bg1 + (size_t)(k0 + 32 + b1k) * Edim);
        }

#pragma unroll
        for (int kh = 0; kh < 2; kh++) {
            unsigned a_f[4][4], b_f[4][2];
#pragma unroll
            for (int mi = 0; mi < 4; mi++)
                ldsm_x4(a_f[mi], &As_f[buf][wm * 64 + mi * 16 + lrow][kh * 16 + lk8]);
#pragma unroll
            for (int np = 0; np < 2; np++) {
                unsigned r[4];
                ldsm_x4_t(r, &Bs_f[buf][kh * 16 + lrow][wn * 32 + np * 16 + lk8]);
                b_f[2*np][0] = r[0]; b_f[2*np][1] = r[1];
                b_f[2*np+1][0] = r[2]; b_f[2*np+1][1] = r[3];
            }
#pragma unroll
            for (int mi = 0; mi < 4; mi++)
#pragma unroll
                for (int ni = 0; ni < 4; ni++)
                    mma_f16(C[mi][ni], a_f[mi], b_f[ni]);
        }

        if (more) {
            int nb = buf ^ 1;
            *(uint4*)&As_f[nb][a0row][a0kc] = a0F;
            *(uint4*)&As_f[nb][a1row][a1kc] = a1F;
            *(uint4*)&Bs_f[nb][b0k][b0n] = b0F;
            *(uint4*)&Bs_f[nb][b1k][b1n] = b1F;
        }
        __syncthreads();
        buf ^= 1;
    }

#pragma unroll
    for (int mi = 0; mi < 4; mi++)
#pragma unroll
        for (int ni = 0; ni < 4; ni++) {
            int gm = m0 + wm * 64 + mi * 16 + (lane >> 2);
            int gc = n0 + wn * 32 + ni * 8 + (lane & 3) * 2;
            float b0f = bo[gc], b1f = bo[gc + 1];
            float* p0 = out + (size_t)gm * Edim + gc;
            *(float2*)p0 = make_float2(C[mi][ni][0] + b0f, C[mi][ni][1] + b1f);
            float* p1 = out + (size_t)(gm + 8) * Edim + gc;
            *(float2*)p1 = make_float2(C[mi][ni][2] + b0f, C[mi][ni][3] + b1f);
        }
}

extern "C" void kernel_launch(void* const* d_in, const int* in_sizes, int n_in,
                              void* d_out, int out_size)
{
    const float* x  = (const float*)d_in[0];
    const float* Wq = (const float*)d_in[1];
    const float* bq = (const float*)d_in[2];
    const float* Wk = (const float*)d_in[3];
    const float* bk = (const float*)d_in[4];
    const float* Wv = (const float*)d_in[5];
    const float* bv = (const float*)d_in[6];
    const float* Wo = (const float*)d_in[7];
    const float* bo = (const float*)d_in[8];
    float* out = (float*)d_out;

    static bool attr_set = false;
    if (!attr_set) {
        cudaFuncSetAttribute(attn_kernel,
            cudaFuncAttributeMaxDynamicSharedMemorySize, ATTN_SMEM_BYTES);
        attr_set = true;
    }

    const int nW = Hn * Edim * DHd / 4;           // 262,144 float4s per weight
    const int nX = Mrows * Edim / 4;              // 1,048,576 float4s
    const int total4 = 4 * nW + nX;               // 2,097,152
    split_flat_kernel<<<(total4 + 255) / 256, 256>>>(Wq, Wk, Wv, Wo, x, nW, total4);

    dim3 g1(Mrows / 128, (3 * Hn * DHd) / 128);   // (32, 24)
    qkv_kernel<<<g1, 256>>>(bq, bk, bv);

    dim3 g2(Sdim / 128, Bsz * Hn);                // (16, 32)
    attn_kernel<<<g2, 256, ATTN_SMEM_BYTES>>>();

    dim3 g3(Mrows / 128, Edim / 128);             // (32, 8)
    outproj_kernel<<<g3, 256>>>(bo, out);
}